// round 7
// baseline (speedup 1.0000x reference)
#include <cuda_runtime.h>
#include <math.h>

// Problem constants
#define EB 4
#define BB 16
#define SB 256
#define CB 17
#define NB 16
#define DB 32
#define DFFB 64
#define HB 4
#define DHB 8

// Scratch (device globals; no allocations allowed)
__device__ float g_xns[BB * SB * NB];        // new_x channels 0..15
__device__ int   g_assign[BB * SB];          // expert id per (b,s)
__device__ int   g_list[EB * BB * SB];       // compacted s-indices per (e,b)
__device__ int   g_cnt[EB * BB];             // counts per (e,b)

// ---------------------------------------------------------------------------
// Kernel 1: decomposition preprocessing. One block per (b, c), c<16.
// DFT: 2 threads per frequency (split u-range, shuffle combine);
// f=0 and f=128 computed analytically (cos=1 / cos=(-1)^u, sin=0).
// ---------------------------------------------------------------------------
__global__ void preprocess_kernel(const float* __restrict__ x)
{
    __shared__ float xr[SB];
    __shared__ float ctab[SB], stab[SB];
    __shared__ float Xre[129], Xim[129], amp[129];
    __shared__ int   s_kept[128];
    __shared__ int   s_keptN;

    const int c = blockIdx.x;   // 0..15
    const int b = blockIdx.y;   // 0..15
    const int t = threadIdx.x;  // 0..255

    xr[t] = x[(b * SB + t) * CB + c];
    {
        const float W2PI = 6.283185307179586f / 256.f;
        float sn, cs;
        sincosf(t * W2PI, &sn, &cs);
        ctab[t] = cs; stab[t] = sn;
    }
    __syncthreads();

    // ---- trend: mean of moving averages with kernels 4, 8, 12 ----
    float tr = 0.f;
    {
        #pragma unroll
        for (int ki = 0; ki < 3; ki++) {
            const int k = (ki == 0) ? 4 : (ki == 1 ? 8 : 12);
            const int pf = (k - 1) >> 1;
            float a = 0.f;
            for (int j = 0; j < k; j++) {
                int idx = t + j - pf;
                idx = idx < 0 ? 0 : (idx > SB - 1 ? SB - 1 : idx);
                a += xr[idx];
            }
            tr += a / (float)k;
        }
        tr *= (1.f / 3.f);
    }

    // ---- rDFT: thread (f, half) sums u in [half*128, half*128+128) ----
    {
        const int f    = t >> 1;    // 0..127
        const int half = t & 1;
        const int u0   = half * 128;
        float re = 0.f, im = 0.f;
        float ssum = 0.f, asum = 0.f;   // for f=0 / f=128 (only f==0 threads use)
        #pragma unroll 4
        for (int uu = 0; uu < 128; uu++) {
            const int u = u0 + uu;
            const float xv = xr[u];
            const int ph = (f * u) & 255;
            re = fmaf(xv,  ctab[ph], re);
            im = fmaf(xv, -stab[ph], im);
            ssum += xv;
            asum += (u & 1) ? -xv : xv;
        }
        // combine halves (t and t^1 are in the same warp)
        re   += __shfl_xor_sync(0xffffffffu, re, 1);
        im   += __shfl_xor_sync(0xffffffffu, im, 1);
        ssum += __shfl_xor_sync(0xffffffffu, ssum, 1);
        asum += __shfl_xor_sync(0xffffffffu, asum, 1);
        if (half == 0) {
            if (f == 0) {
                Xre[0] = ssum; Xim[0] = 0.f; amp[0] = 0.f;      // excluded (-inf in ref)
                Xre[128] = asum; Xim[128] = 0.f; amp[128] = fabsf(asum);
            } else {
                Xre[f] = re; Xim[f] = im;
                amp[f] = sqrtf(re * re + im * im);
            }
        }
    }
    __syncthreads();

    // ---- top-4 threshold among f=1..128 ----
    if (t == 0) {
        float b0 = -1e30f, b1v = -1e30f, b2v = -1e30f, b3v = -1e30f;
        for (int f = 1; f <= 128; f++) {
            float a = amp[f];
            if (a > b3v) {
                if (a > b0)       { b3v = b2v; b2v = b1v; b1v = b0; b0 = a; }
                else if (a > b1v) { b3v = b2v; b2v = b1v; b1v = a; }
                else if (a > b2v) { b3v = b2v; b2v = a; }
                else              { b3v = a; }
            }
        }
        int cnt = 0;
        for (int f = 1; f <= 128; f++)
            if (amp[f] >= b3v) s_kept[cnt++] = f;
        s_keptN = cnt;
    }
    __syncthreads();

    // ---- inverse transform of masked spectrum ----
    float season = 0.f;
    const int kn = s_keptN;
    for (int ii = 0; ii < kn; ii++) {
        int f = s_kept[ii];
        int ph = (f * t) & 255;
        if (f == 128) {
            season += Xre[128] * ctab[ph];     // cos(pi*t) = +-1
        } else {
            season += 2.f * (Xre[f] * ctab[ph] - Xim[f] * stab[ph]);
        }
    }
    season *= (1.f / 256.f);

    g_xns[(b * SB + t) * NB + c] = xr[t] + season + tr;
}

// ---------------------------------------------------------------------------
// Kernel 2: min/max -> bins -> assignment -> deterministic compacted lists.
// ---------------------------------------------------------------------------
__global__ void assign_kernel(const float* __restrict__ orig)
{
    __shared__ float smn[256], smx[256];
    __shared__ float bins[EB + 1];
    __shared__ int   sA[BB * SB];
    const int t = threadIdx.x;

    float mn = 1e30f, mx = -1e30f;
    for (int i = t; i < BB * SB; i += 256) {
        float v = orig[2 * i + 1];
        mn = fminf(mn, v);
        mx = fmaxf(mx, v);
    }
    smn[t] = mn; smx[t] = mx;
    __syncthreads();
    for (int off = 128; off > 0; off >>= 1) {
        if (t < off) {
            smn[t] = fminf(smn[t], smn[t + off]);
            smx[t] = fmaxf(smx[t], smx[t + off]);
        }
        __syncthreads();
    }
    if (t == 0) {
        float lo = smn[0], hi = smx[0];
        float st = (hi - lo) * 0.25f;
        for (int j = 0; j <= EB; j++) bins[j] = lo + j * st;
    }
    __syncthreads();
    for (int i = t; i < BB * SB; i += 256) {
        float v = orig[2 * i + 1];
        int cnt = 0;
        #pragma unroll
        for (int j = 0; j <= EB; j++) cnt += (bins[j] <= v) ? 1 : 0;
        int a = cnt - 1;
        a = a < 0 ? 0 : (a > EB - 1 ? EB - 1 : a);
        g_assign[i] = a;
        sA[i] = a;
    }
    __syncthreads();

    if (t < BB) {
        int cnt[EB] = {0, 0, 0, 0};
        const int base = t * SB;
        for (int s = 0; s < SB; s++) {
            int a = sA[base + s];
            g_list[(a * BB + t) * SB + cnt[a]] = s;
            cnt[a]++;
        }
        #pragma unroll
        for (int e = 0; e < EB; e++) g_cnt[e * BB + t] = cnt[e];
    }
}

// ---------------------------------------------------------------------------
// Kernel 3: expert forward, head-parallel: 4 threads per query (one per head).
// Block (n, b, e), 256 threads = 64 queries/chunk x 4 heads.
// Unassigned keys collapse to one aggregated (k_const, v_const) term.
// ---------------------------------------------------------------------------
#define KV_STRIDE 36
#define SMEM_FLOATS (8544 + 2 * SB * KV_STRIDE)

__global__ void __launch_bounds__(256, 2) expert_kernel(
    const float* __restrict__ startW, const float* __restrict__ startb,
    const float* __restrict__ Wq, const float* __restrict__ Wk,
    const float* __restrict__ Wv, const float* __restrict__ Wo,
    const float* __restrict__ ln1g, const float* __restrict__ ln1b,
    const float* __restrict__ ln2g, const float* __restrict__ ln2b,
    const float* __restrict__ W1, const float* __restrict__ b1,
    const float* __restrict__ W2, const float* __restrict__ b2,
    float* __restrict__ out)
{
    extern __shared__ float sm[];
    float* sWq   = sm;
    float* sWk   = sm + 1024;
    float* sWv   = sm + 2048;
    float* sWo   = sm + 3072;
    float* sW1   = sm + 4096;   // 32x64
    float* sW2   = sm + 6144;   // 64x32
    float* sln1g = sm + 8192;
    float* sln1b = sm + 8224;
    float* sln2g = sm + 8256;
    float* sln2b = sm + 8288;
    float* sb1v  = sm + 8320;   // 64
    float* sb2v  = sm + 8384;   // 32
    float* ssW   = sm + 8416;
    float* ssb   = sm + 8448;
    float* sKc   = sm + 8480;   // k_const [32]
    float* sVc   = sm + 8512;   // v_const [32]
    float* Ksm   = sm + 8544;                  // [256][36]
    float* Vsm   = sm + 8544 + SB * KV_STRIDE; // [256][36]

    const int t = threadIdx.x;
    const int n = blockIdx.x, b = blockIdx.y, e = blockIdx.z;

    // cooperative weight staging
    {
        const float* gq = Wq + e * 1024;
        const float* gk = Wk + e * 1024;
        const float* gv = Wv + e * 1024;
        const float* go = Wo + e * 1024;
        for (int i = t; i < 1024; i += 256) {
            sWq[i] = gq[i]; sWk[i] = gk[i]; sWv[i] = gv[i]; sWo[i] = go[i];
        }
        const float* g1 = W1 + e * 2048;
        const float* g2 = W2 + e * 2048;
        for (int i = t; i < 2048; i += 256) { sW1[i] = g1[i]; sW2[i] = g2[i]; }
        if (t < 32) {
            sln1g[t] = ln1g[e * 32 + t]; sln1b[t] = ln1b[e * 32 + t];
            sln2g[t] = ln2g[e * 32 + t]; sln2b[t] = ln2b[e * 32 + t];
            sb2v[t]  = b2[e * 32 + t];
            ssW[t]   = startW[t];
            ssb[t]   = startb[t];
        }
        if (t < 64) sb1v[t] = b1[e * 64 + t];
    }
    __syncthreads();

    const int cnt = g_cnt[e * BB + b];
    const int nchunks = (cnt + 63) >> 6;

    // ---- per-expert constant key/value (h_const = start_b) ----
    if (t < 32) {
        float m = 0.f;
        #pragma unroll
        for (int d = 0; d < 32; d++) m += ssb[d];
        m *= (1.f / 32.f);
        float var = 0.f;
        #pragma unroll
        for (int d = 0; d < 32; d++) { float dd = ssb[d] - m; var = fmaf(dd, dd, var); }
        var *= (1.f / 32.f);
        float r = rsqrtf(var + 1e-5f);
        float kc = 0.f, vc = 0.f;
        #pragma unroll
        for (int k2 = 0; k2 < 32; k2++) {
            float zc = fmaf((ssb[k2] - m) * r, sln1g[k2], sln1b[k2]);
            kc = fmaf(zc, sWk[k2 * 32 + t], kc);
            vc = fmaf(zc, sWv[k2 * 32 + t], vc);
        }
        sKc[t] = kc; sVc[t] = vc;
    }

    const int h8 = (t & 3) * 8;     // this thread's head slice [h8, h8+8)
    const int qt = t >> 2;          // query slot within chunk (0..63)

    float qreg[4][8];
    float xv[4];
    int   sreg[4];

    // ================= Pass 1: q (regs), K/V head-slices (smem) ============
    #pragma unroll
    for (int chunk = 0; chunk < 4; chunk++) {
        if (chunk >= nchunks) break;
        const int qi = chunk * 64 + qt;
        const bool act = qi < cnt;
        const int s_ = act ? g_list[(e * BB + b) * SB + qi] : 0;
        const float xval = act ? g_xns[(b * SB + s_) * NB + n] : 0.f;
        sreg[chunk] = s_;
        xv[chunk] = xval;

        // z = LN1(xval*startW + startb)
        float z[32];
        {
            float mean = 0.f;
            #pragma unroll
            for (int d = 0; d < 32; d++) { z[d] = fmaf(xval, ssW[d], ssb[d]); mean += z[d]; }
            mean *= (1.f / 32.f);
            float var = 0.f;
            #pragma unroll
            for (int d = 0; d < 32; d++) { float dd = z[d] - mean; var = fmaf(dd, dd, var); }
            var *= (1.f / 32.f);
            float r = rsqrtf(var + 1e-5f);
            #pragma unroll
            for (int d = 0; d < 32; d++)
                z[d] = fmaf((z[d] - mean) * r, sln1g[d], sln1b[d]);
        }

        // q head slice
        {
            float acc[8];
            #pragma unroll
            for (int j = 0; j < 8; j++) acc[j] = 0.f;
            #pragma unroll
            for (int k2 = 0; k2 < 32; k2++) {
                const float zz = z[k2];
                const float4 w0 = *reinterpret_cast<const float4*>(sWq + k2 * 32 + h8);
                const float4 w1 = *reinterpret_cast<const float4*>(sWq + k2 * 32 + h8 + 4);
                acc[0] = fmaf(zz, w0.x, acc[0]); acc[1] = fmaf(zz, w0.y, acc[1]);
                acc[2] = fmaf(zz, w0.z, acc[2]); acc[3] = fmaf(zz, w0.w, acc[3]);
                acc[4] = fmaf(zz, w1.x, acc[4]); acc[5] = fmaf(zz, w1.y, acc[5]);
                acc[6] = fmaf(zz, w1.z, acc[6]); acc[7] = fmaf(zz, w1.w, acc[7]);
            }
            #pragma unroll
            for (int j = 0; j < 8; j++) qreg[chunk][j] = acc[j];
        }
        // k head slice -> Ksm
        {
            float acc[8];
            #pragma unroll
            for (int j = 0; j < 8; j++) acc[j] = 0.f;
            #pragma unroll
            for (int k2 = 0; k2 < 32; k2++) {
                const float zz = z[k2];
                const float4 w0 = *reinterpret_cast<const float4*>(sWk + k2 * 32 + h8);
                const float4 w1 = *reinterpret_cast<const float4*>(sWk + k2 * 32 + h8 + 4);
                acc[0] = fmaf(zz, w0.x, acc[0]); acc[1] = fmaf(zz, w0.y, acc[1]);
                acc[2] = fmaf(zz, w0.z, acc[2]); acc[3] = fmaf(zz, w0.w, acc[3]);
                acc[4] = fmaf(zz, w1.x, acc[4]); acc[5] = fmaf(zz, w1.y, acc[5]);
                acc[6] = fmaf(zz, w1.z, acc[6]); acc[7] = fmaf(zz, w1.w, acc[7]);
            }
            float4* kw = reinterpret_cast<float4*>(Ksm + qi * KV_STRIDE + h8);
            kw[0] = make_float4(acc[0], acc[1], acc[2], acc[3]);
            kw[1] = make_float4(acc[4], acc[5], acc[6], acc[7]);
        }
        // v head slice -> Vsm
        {
            float acc[8];
            #pragma unroll
            for (int j = 0; j < 8; j++) acc[j] = 0.f;
            #pragma unroll
            for (int k2 = 0; k2 < 32; k2++) {
                const float zz = z[k2];
                const float4 w0 = *reinterpret_cast<const float4*>(sWv + k2 * 32 + h8);
                const float4 w1 = *reinterpret_cast<const float4*>(sWv + k2 * 32 + h8 + 4);
                acc[0] = fmaf(zz, w0.x, acc[0]); acc[1] = fmaf(zz, w0.y, acc[1]);
                acc[2] = fmaf(zz, w0.z, acc[2]); acc[3] = fmaf(zz, w0.w, acc[3]);
                acc[4] = fmaf(zz, w1.x, acc[4]); acc[5] = fmaf(zz, w1.y, acc[5]);
                acc[6] = fmaf(zz, w1.z, acc[6]); acc[7] = fmaf(zz, w1.w, acc[7]);
            }
            float4* vw = reinterpret_cast<float4*>(Vsm + qi * KV_STRIDE + h8);
            vw[0] = make_float4(acc[0], acc[1], acc[2], acc[3]);
            vw[1] = make_float4(acc[4], acc[5], acc[6], acc[7]);
        }
    }
    __syncthreads();

    // ================= Pass 2: attention + Wo + LN2 + FFN ==================
    const float att_scale = 0.3535533905932738f; // 1/sqrt(8)

    #pragma unroll
    for (int chunk = 0; chunk < 4; chunk++) {
        if (chunk >= nchunks) break;
        const int qi = chunk * 64 + qt;
        const bool act = qi < cnt;

        float o[8];
        #pragma unroll
        for (int j = 0; j < 8; j++) o[j] = 0.f;
        float lsum = 0.f;
        const float q0 = qreg[chunk][0], q1 = qreg[chunk][1],
                    q2 = qreg[chunk][2], q3 = qreg[chunk][3],
                    q4 = qreg[chunk][4], q5 = qreg[chunk][5],
                    q6 = qreg[chunk][6], q7 = qreg[chunk][7];

        for (int key = 0; key < cnt; key++) {
            const float4 ka = *reinterpret_cast<const float4*>(Ksm + key * KV_STRIDE + h8);
            const float4 kb = *reinterpret_cast<const float4*>(Ksm + key * KV_STRIDE + h8 + 4);
            float lg = q0 * ka.x;
            lg = fmaf(q1, ka.y, lg); lg = fmaf(q2, ka.z, lg); lg = fmaf(q3, ka.w, lg);
            lg = fmaf(q4, kb.x, lg); lg = fmaf(q5, kb.y, lg);
            lg = fmaf(q6, kb.z, lg); lg = fmaf(q7, kb.w, lg);
            const float p = __expf(fminf(lg * att_scale, 80.f));
            lsum += p;
            const float4 va = *reinterpret_cast<const float4*>(Vsm + key * KV_STRIDE + h8);
            const float4 vb = *reinterpret_cast<const float4*>(Vsm + key * KV_STRIDE + h8 + 4);
            o[0] = fmaf(p, va.x, o[0]); o[1] = fmaf(p, va.y, o[1]);
            o[2] = fmaf(p, va.z, o[2]); o[3] = fmaf(p, va.w, o[3]);
            o[4] = fmaf(p, vb.x, o[4]); o[5] = fmaf(p, vb.y, o[5]);
            o[6] = fmaf(p, vb.z, o[6]); o[7] = fmaf(p, vb.w, o[7]);
        }
        // aggregated constant-key term: weight (256 - cnt)
        {
            const float4 ka = *reinterpret_cast<const float4*>(sKc + h8);
            const float4 kb = *reinterpret_cast<const float4*>(sKc + h8 + 4);
            float lg = q0 * ka.x;
            lg = fmaf(q1, ka.y, lg); lg = fmaf(q2, ka.z, lg); lg = fmaf(q3, ka.w, lg);
            lg = fmaf(q4, kb.x, lg); lg = fmaf(q5, kb.y, lg);
            lg = fmaf(q6, kb.z, lg); lg = fmaf(q7, kb.w, lg);
            const float p = (float)(SB - cnt) * __expf(fminf(lg * att_scale, 80.f));
            lsum += p;
            const float4 va = *reinterpret_cast<const float4*>(sVc + h8);
            const float4 vb = *reinterpret_cast<const float4*>(sVc + h8 + 4);
            o[0] = fmaf(p, va.x, o[0]); o[1] = fmaf(p, va.y, o[1]);
            o[2] = fmaf(p, va.z, o[2]); o[3] = fmaf(p, va.w, o[3]);
            o[4] = fmaf(p, vb.x, o[4]); o[5] = fmaf(p, vb.y, o[5]);
            o[6] = fmaf(p, vb.z, o[6]); o[7] = fmaf(p, vb.w, o[7]);
        }
        {
            const float inv = 1.0f / lsum;
            #pragma unroll
            for (int j = 0; j < 8; j++) o[j] *= inv;
        }

        // partial h2 = o_head @ Wo[rows h8..h8+7]
        float h2[32];
        #pragma unroll
        for (int d = 0; d < 32; d++) h2[d] = 0.f;
        #pragma unroll
        for (int j = 0; j < 8; j++) {
            const float fj = o[j];
            const float4* wr = reinterpret_cast<const float4*>(sWo + (h8 + j) * 32);
            #pragma unroll
            for (int d4 = 0; d4 < 8; d4++) {
                const float4 w = wr[d4];
                h2[d4*4 + 0] = fmaf(fj, w.x, h2[d4*4 + 0]);
                h2[d4*4 + 1] = fmaf(fj, w.y, h2[d4*4 + 1]);
                h2[d4*4 + 2] = fmaf(fj, w.z, h2[d4*4 + 2]);
                h2[d4*4 + 3] = fmaf(fj, w.w, h2[d4*4 + 3]);
            }
        }
        // quad reduce partial h2 across the 4 heads
        #pragma unroll
        for (int d = 0; d < 32; d++) {
            h2[d] += __shfl_xor_sync(0xffffffffu, h2[d], 1);
            h2[d] += __shfl_xor_sync(0xffffffffu, h2[d], 2);
        }
        // h2 += h (residual)
        const float xval = xv[chunk];
        #pragma unroll
        for (int d = 0; d < 32; d++) h2[d] += fmaf(xval, ssW[d], ssb[d]);

        // z2 = LN2(h2)
        float z2[32];
        {
            float mean = 0.f;
            #pragma unroll
            for (int d = 0; d < 32; d++) mean += h2[d];
            mean *= (1.f / 32.f);
            float var = 0.f;
            #pragma unroll
            for (int d = 0; d < 32; d++) { float dd = h2[d] - mean; var = fmaf(dd, dd, var); }
            var *= (1.f / 32.f);
            float r = rsqrtf(var + 1e-5f);
            #pragma unroll
            for (int d = 0; d < 32; d++)
                z2[d] = fmaf((h2[d] - mean) * r, sln2g[d], sln2b[d]);
        }

        // FFN slice: this thread's 16 of 64 f-dims
        const int f0 = (t & 3) * 16;
        float fh[16];
        #pragma unroll
        for (int j = 0; j < 16; j++) fh[j] = sb1v[f0 + j];
        #pragma unroll
        for (int k2 = 0; k2 < 32; k2++) {
            const float zz = z2[k2];
            const float4* wr = reinterpret_cast<const float4*>(sW1 + k2 * 64 + f0);
            #pragma unroll
            for (int j4 = 0; j4 < 4; j4++) {
                const float4 w = wr[j4];
                fh[j4*4 + 0] = fmaf(zz, w.x, fh[j4*4 + 0]);
                fh[j4*4 + 1] = fmaf(zz, w.y, fh[j4*4 + 1]);
                fh[j4*4 + 2] = fmaf(zz, w.z, fh[j4*4 + 2]);
                fh[j4*4 + 3] = fmaf(zz, w.w, fh[j4*4 + 3]);
            }
        }
        #pragma unroll
        for (int j = 0; j < 16; j++) fh[j] = fmaxf(fh[j], 0.f);

        float h3p[32];
        #pragma unroll
        for (int d = 0; d < 32; d++) h3p[d] = 0.f;
        #pragma unroll
        for (int j = 0; j < 16; j++) {
            const float fj = fh[j];
            const float4* wr = reinterpret_cast<const float4*>(sW2 + (f0 + j) * 32);
            #pragma unroll
            for (int d4 = 0; d4 < 8; d4++) {
                const float4 w = wr[d4];
                h3p[d4*4 + 0] = fmaf(fj, w.x, h3p[d4*4 + 0]);
                h3p[d4*4 + 1] = fmaf(fj, w.y, h3p[d4*4 + 1]);
                h3p[d4*4 + 2] = fmaf(fj, w.z, h3p[d4*4 + 2]);
                h3p[d4*4 + 3] = fmaf(fj, w.w, h3p[d4*4 + 3]);
            }
        }
        // quad reduce partial h3
        #pragma unroll
        for (int d = 0; d < 32; d++) {
            h3p[d] += __shfl_xor_sync(0xffffffffu, h3p[d], 1);
            h3p[d] += __shfl_xor_sync(0xffffffffu, h3p[d], 2);
        }

        // write: lane writes its 8 output dims (full coverage per query)
        if (act) {
            const int bs = b * SB + sreg[chunk];
            float* op = out + ((bs * NB) + n) * DB + h8;
            const float4 r0 = make_float4(h2[h8+0] + sb2v[h8+0] + h3p[h8+0],
                                          h2[h8+1] + sb2v[h8+1] + h3p[h8+1],
                                          h2[h8+2] + sb2v[h8+2] + h3p[h8+2],
                                          h2[h8+3] + sb2v[h8+3] + h3p[h8+3]);
            const float4 r1 = make_float4(h2[h8+4] + sb2v[h8+4] + h3p[h8+4],
                                          h2[h8+5] + sb2v[h8+5] + h3p[h8+5],
                                          h2[h8+6] + sb2v[h8+6] + h3p[h8+6],
                                          h2[h8+7] + sb2v[h8+7] + h3p[h8+7]);
            reinterpret_cast<float4*>(op)[0] = r0;
            reinterpret_cast<float4*>(op)[1] = r1;
        }
    }
}

// ---------------------------------------------------------------------------
extern "C" void kernel_launch(void* const* d_in, const int* in_sizes, int n_in,
                              void* d_out, int out_size)
{
    const float* x      = (const float*)d_in[0];
    const float* orig   = (const float*)d_in[1];
    const float* startW = (const float*)d_in[2];
    const float* startb = (const float*)d_in[3];
    const float* Wq     = (const float*)d_in[4];
    const float* Wk     = (const float*)d_in[5];
    const float* Wv     = (const float*)d_in[6];
    const float* Wo     = (const float*)d_in[7];
    const float* l1g    = (const float*)d_in[8];
    const float* l1b    = (const float*)d_in[9];
    const float* l2g    = (const float*)d_in[10];
    const float* l2b    = (const float*)d_in[11];
    const float* W1     = (const float*)d_in[12];
    const float* b1     = (const float*)d_in[13];
    const float* W2     = (const float*)d_in[14];
    const float* b2     = (const float*)d_in[15];
    float* out = (float*)d_out;

    preprocess_kernel<<<dim3(NB, BB), 256>>>(x);
    assign_kernel<<<1, 256>>>(orig);

    const int smem_bytes = SMEM_FLOATS * (int)sizeof(float);
    cudaFuncSetAttribute(expert_kernel,
                         cudaFuncAttributeMaxDynamicSharedMemorySize, smem_bytes);
    expert_kernel<<<dim3(NB, BB, EB), 256, smem_bytes>>>(
        startW, startb, Wq, Wk, Wv, Wo,
        l1g, l1b, l2g, l2b, W1, b1, W2, b2, out);
}

// round 9
// speedup vs baseline: 6.8441x; 6.8441x over previous
#include <cuda_runtime.h>
#include <math.h>

// Problem constants
#define EB 4
#define BB 16
#define SB 256
#define CB 17
#define NB 16
#define DB 32
#define DFFB 64
#define HB 4
#define DHB 8

// Scratch (device globals; no allocations allowed)
__device__ float g_xns[BB * SB * NB];   // new_x channels 0..15
__device__ int   g_glist[BB * SB];      // per-b compacted s-indices, sorted by (expert, s)
__device__ int   g_off[BB * EB];        // per-b start offset of expert e in g_glist
__device__ int   g_ecnt[BB * EB];       // per-b count of expert e

// ---------------------------------------------------------------------------
// Kernel 1: decomposition preprocessing. One block per (b, c), c<16.
// ---------------------------------------------------------------------------
__global__ void preprocess_kernel(const float* __restrict__ x)
{
    __shared__ float xr[SB];
    __shared__ float ctab[SB], stab[SB];
    __shared__ float Xre[129], Xim[129], amp[129];
    __shared__ int   s_kept[128];
    __shared__ int   s_keptN;

    const int c = blockIdx.x;   // 0..15
    const int b = blockIdx.y;   // 0..15
    const int t = threadIdx.x;  // 0..255

    xr[t] = x[(b * SB + t) * CB + c];
    {
        const float W2PI = 6.283185307179586f / 256.f;
        float sn, cs;
        sincosf(t * W2PI, &sn, &cs);
        ctab[t] = cs; stab[t] = sn;
    }
    __syncthreads();

    // ---- trend: mean of moving averages with kernels 4, 8, 12 ----
    float tr = 0.f;
    {
        #pragma unroll
        for (int ki = 0; ki < 3; ki++) {
            const int k = (ki == 0) ? 4 : (ki == 1 ? 8 : 12);
            const int pf = (k - 1) >> 1;
            float a = 0.f;
            for (int j = 0; j < k; j++) {
                int idx = t + j - pf;
                idx = idx < 0 ? 0 : (idx > SB - 1 ? SB - 1 : idx);
                a += xr[idx];
            }
            tr += a / (float)k;
        }
        tr *= (1.f / 3.f);
    }

    // ---- rDFT: thread (f, half) sums u in [half*128, half*128+128) ----
    {
        const int f    = t >> 1;    // 0..127
        const int half = t & 1;
        const int u0   = half * 128;
        float re = 0.f, im = 0.f;
        float ssum = 0.f, asum = 0.f;
        #pragma unroll 4
        for (int uu = 0; uu < 128; uu++) {
            const int u = u0 + uu;
            const float xv = xr[u];
            const int ph = (f * u) & 255;
            re = fmaf(xv,  ctab[ph], re);
            im = fmaf(xv, -stab[ph], im);
            ssum += xv;
            asum += (u & 1) ? -xv : xv;
        }
        re   += __shfl_xor_sync(0xffffffffu, re, 1);
        im   += __shfl_xor_sync(0xffffffffu, im, 1);
        ssum += __shfl_xor_sync(0xffffffffu, ssum, 1);
        asum += __shfl_xor_sync(0xffffffffu, asum, 1);
        if (half == 0) {
            if (f == 0) {
                Xre[0] = ssum; Xim[0] = 0.f; amp[0] = 0.f;   // f=0 excluded in ref
                Xre[128] = asum; Xim[128] = 0.f; amp[128] = fabsf(asum);
            } else {
                Xre[f] = re; Xim[f] = im;
                amp[f] = sqrtf(re * re + im * im);
            }
        }
    }
    __syncthreads();

    // ---- top-4 threshold among f=1..128 ----
    if (t == 0) {
        float b0 = -1e30f, b1v = -1e30f, b2v = -1e30f, b3v = -1e30f;
        for (int f = 1; f <= 128; f++) {
            float a = amp[f];
            if (a > b3v) {
                if (a > b0)       { b3v = b2v; b2v = b1v; b1v = b0; b0 = a; }
                else if (a > b1v) { b3v = b2v; b2v = b1v; b1v = a; }
                else if (a > b2v) { b3v = b2v; b2v = a; }
                else              { b3v = a; }
            }
        }
        int cnt = 0;
        for (int f = 1; f <= 128; f++)
            if (amp[f] >= b3v) s_kept[cnt++] = f;
        s_keptN = cnt;
    }
    __syncthreads();

    // ---- inverse transform of masked spectrum ----
    float season = 0.f;
    const int kn = s_keptN;
    for (int ii = 0; ii < kn; ii++) {
        int f = s_kept[ii];
        int ph = (f * t) & 255;
        if (f == 128) {
            season += Xre[128] * ctab[ph];
        } else {
            season += 2.f * (Xre[f] * ctab[ph] - Xim[f] * stab[ph]);
        }
    }
    season *= (1.f / 256.f);

    g_xns[(b * SB + t) * NB + c] = xr[t] + season + tr;
}

// ---------------------------------------------------------------------------
// Kernel 2: min/max -> bins -> assignment -> per-b compacted list sorted by
// (expert, s) + offsets. Deterministic (serial scan per b).
// ---------------------------------------------------------------------------
__global__ void assign_kernel(const float* __restrict__ orig)
{
    __shared__ float smn[256], smx[256];
    __shared__ float bins[EB + 1];
    __shared__ int   sA[BB * SB];
    const int t = threadIdx.x;

    float mn = 1e30f, mx = -1e30f;
    for (int i = t; i < BB * SB; i += 256) {
        float v = orig[2 * i + 1];
        mn = fminf(mn, v);
        mx = fmaxf(mx, v);
    }
    smn[t] = mn; smx[t] = mx;
    __syncthreads();
    for (int off = 128; off > 0; off >>= 1) {
        if (t < off) {
            smn[t] = fminf(smn[t], smn[t + off]);
            smx[t] = fmaxf(smx[t], smx[t + off]);
        }
        __syncthreads();
    }
    if (t == 0) {
        float lo = smn[0], hi = smx[0];
        float st = (hi - lo) * 0.25f;
        for (int j = 0; j <= EB; j++) bins[j] = lo + j * st;
    }
    __syncthreads();
    for (int i = t; i < BB * SB; i += 256) {
        float v = orig[2 * i + 1];
        int cnt = 0;
        #pragma unroll
        for (int j = 0; j <= EB; j++) cnt += (bins[j] <= v) ? 1 : 0;
        int a = cnt - 1;
        a = a < 0 ? 0 : (a > EB - 1 ? EB - 1 : a);
        sA[i] = a;
    }
    __syncthreads();

    if (t < BB) {
        const int base = t * SB;
        int cnt[EB] = {0, 0, 0, 0};
        for (int s = 0; s < SB; s++) cnt[sA[base + s]]++;
        int off[EB];
        off[0] = 0;
        #pragma unroll
        for (int e = 1; e < EB; e++) off[e] = off[e - 1] + cnt[e - 1];
        #pragma unroll
        for (int e = 0; e < EB; e++) {
            g_off[t * EB + e]  = off[e];
            g_ecnt[t * EB + e] = cnt[e];
        }
        int pos[EB];
        #pragma unroll
        for (int e = 0; e < EB; e++) pos[e] = off[e];
        for (int s = 0; s < SB; s++) {
            int a = sA[base + s];
            g_glist[base + pos[a]] = s;
            pos[a]++;
        }
    }
}

// ---------------------------------------------------------------------------
// 32x32 matvec from shared-memory weight (row-major [k][j]) into reg acc[32].
// ---------------------------------------------------------------------------
__device__ __forceinline__ void matvec32(const float* __restrict__ Wsm,
                                         const float (&vin)[32],
                                         float (&acc)[32])
{
    #pragma unroll
    for (int k2 = 0; k2 < 32; k2++) {
        const float zz = vin[k2];
        const float4* wr = reinterpret_cast<const float4*>(Wsm + k2 * 32);
        #pragma unroll
        for (int j4 = 0; j4 < 8; j4++) {
            float4 w = wr[j4];
            acc[j4 * 4 + 0] = fmaf(zz, w.x, acc[j4 * 4 + 0]);
            acc[j4 * 4 + 1] = fmaf(zz, w.y, acc[j4 * 4 + 1]);
            acc[j4 * 4 + 2] = fmaf(zz, w.z, acc[j4 * 4 + 2]);
            acc[j4 * 4 + 3] = fmaf(zz, w.w, acc[j4 * 4 + 3]);
        }
    }
}

// ---------------------------------------------------------------------------
// Kernel 3: ALL 4 experts merged per block. One block per (n, b), 256 threads,
// thread t handles the t-th entry of the per-b (expert-sorted) compacted list.
// Every thread is active. Unassigned keys of thread's expert collapse to one
// aggregated (k_const, v_const) term with weight (256 - cnt_e).
// Smem: 4 experts' weights (131 KB) + K/V (72 KB) -> occ 1, 255 regs.
// ---------------------------------------------------------------------------
#define WSTR   8192                 // floats per expert weight bank
#define KV_STRIDE 36
#define OFF_LN1G 32768
#define OFF_LN1B 32896
#define OFF_LN2G 33024
#define OFF_LN2B 33152
#define OFF_B1   33280
#define OFF_B2   33536
#define OFF_SSW  33664
#define OFF_SSB  33696
#define OFF_KC   33728
#define OFF_VC   33856
#define OFF_INTS 33984              // 8 ints: off[4], cnt[4]
#define OFF_K    34048
#define OFF_V    (34048 + SB * KV_STRIDE)
#define SMEM_FLOATS (OFF_V + SB * KV_STRIDE)

__global__ void __launch_bounds__(256, 1) expert_kernel(
    const float* __restrict__ startW, const float* __restrict__ startb,
    const float* __restrict__ Wq, const float* __restrict__ Wk,
    const float* __restrict__ Wv, const float* __restrict__ Wo,
    const float* __restrict__ ln1g, const float* __restrict__ ln1b,
    const float* __restrict__ ln2g, const float* __restrict__ ln2b,
    const float* __restrict__ W1, const float* __restrict__ b1,
    const float* __restrict__ W2, const float* __restrict__ b2,
    float* __restrict__ out)
{
    extern __shared__ float sm[];
    float* sKc = sm + OFF_KC;
    float* sVc = sm + OFF_VC;
    float* Ksm = sm + OFF_K;
    float* Vsm = sm + OFF_V;
    int*   sI  = reinterpret_cast<int*>(sm + OFF_INTS);

    const int t = threadIdx.x;
    const int n = blockIdx.x, b = blockIdx.y;

    // ---- stage all 4 experts' weights (float4 copies) ----
    {
        const float4* gq = reinterpret_cast<const float4*>(Wq);
        const float4* gk = reinterpret_cast<const float4*>(Wk);
        const float4* gv = reinterpret_cast<const float4*>(Wv);
        const float4* go = reinterpret_cast<const float4*>(Wo);
        #pragma unroll
        for (int i = t; i < 1024; i += 256) {          // 4 experts x 256 float4
            const int e = i >> 8, idx = i & 255;
            float4* dst = reinterpret_cast<float4*>(sm + e * WSTR);
            dst[idx]        = gq[i];
            dst[256 + idx]  = gk[i];
            dst[512 + idx]  = gv[i];
            dst[768 + idx]  = go[i];
        }
        const float4* g1 = reinterpret_cast<const float4*>(W1);
        const float4* g2 = reinterpret_cast<const float4*>(W2);
        #pragma unroll
        for (int i = t; i < 2048; i += 256) {          // 4 experts x 512 float4
            const int e = i >> 9, idx = i & 511;
            float4* dst = reinterpret_cast<float4*>(sm + e * WSTR + 4096);
            dst[idx]        = g1[i];
            dst[512 + idx]  = g2[i];
        }
        if (t < 128) {
            sm[OFF_LN1G + t] = ln1g[t];
            sm[OFF_LN1B + t] = ln1b[t];
            sm[OFF_LN2G + t] = ln2g[t];
            sm[OFF_LN2B + t] = ln2b[t];
            sm[OFF_B2 + t]   = b2[t];
        }
        sm[OFF_B1 + t] = b1[t];                        // 256 floats
        if (t < 32) {
            sm[OFF_SSW + t] = startW[t];
            sm[OFF_SSB + t] = startb[t];
        }
        if (t < 4) {
            sI[t]     = g_off[b * EB + t];
            sI[4 + t] = g_ecnt[b * EB + t];
        }
    }
    __syncthreads();

    const float* ssW = sm + OFF_SSW;
    const float* ssb = sm + OFF_SSB;

    // ---- per-expert constant key/value (h_const = start_b, expert-indep LN stats) ----
    if (t < 128) {
        const int ce = t >> 5;       // expert
        const int d  = t & 31;       // output dim
        float m = 0.f;
        #pragma unroll
        for (int dd = 0; dd < 32; dd++) m += ssb[dd];
        m *= (1.f / 32.f);
        float var = 0.f;
        #pragma unroll
        for (int dd = 0; dd < 32; dd++) { float df = ssb[dd] - m; var = fmaf(df, df, var); }
        var *= (1.f / 32.f);
        const float r = rsqrtf(var + 1e-5f);
        const float* l1g_ = sm + OFF_LN1G + ce * 32;
        const float* l1b_ = sm + OFF_LN1B + ce * 32;
        const float* wk_  = sm + ce * WSTR + 1024;
        const float* wv_  = sm + ce * WSTR + 2048;
        float kc = 0.f, vc = 0.f;
        #pragma unroll
        for (int k2 = 0; k2 < 32; k2++) {
            float zc = fmaf((ssb[k2] - m) * r, l1g_[k2], l1b_[k2]);
            kc = fmaf(zc, wk_[k2 * 32 + d], kc);
            vc = fmaf(zc, wv_[k2 * 32 + d], vc);
        }
        sKc[ce * 32 + d] = kc;
        sVc[ce * 32 + d] = vc;
    }

    // ---- this thread's query ----
    const int e = (t >= sI[1]) + (t >= sI[2]) + (t >= sI[3]);
    const int s = g_glist[b * SB + t];
    const float xval = g_xns[(b * SB + s) * NB + n];

    const float* wb   = sm + e * WSTR;
    const float* l1g_ = sm + OFF_LN1G + e * 32;
    const float* l1b_ = sm + OFF_LN1B + e * 32;
    const float* l2g_ = sm + OFF_LN2G + e * 32;
    const float* l2b_ = sm + OFF_LN2B + e * 32;
    const float* b1_  = sm + OFF_B1 + e * 64;
    const float* b2_  = sm + OFF_B2 + e * 32;

    // ---- z = LN1(xval*startW + startb) ----
    float z[32];
    {
        float mean = 0.f;
        #pragma unroll
        for (int d = 0; d < 32; d++) { z[d] = fmaf(xval, ssW[d], ssb[d]); mean += z[d]; }
        mean *= (1.f / 32.f);
        float var = 0.f;
        #pragma unroll
        for (int d = 0; d < 32; d++) { float dd = z[d] - mean; var = fmaf(dd, dd, var); }
        var *= (1.f / 32.f);
        float r = rsqrtf(var + 1e-5f);
        #pragma unroll
        for (int d = 0; d < 32; d++)
            z[d] = fmaf((z[d] - mean) * r, l1g_[d], l1b_[d]);
    }

    // ---- q (regs), k/v -> smem row t ----
    float q[32];
    #pragma unroll
    for (int i = 0; i < 32; i++) q[i] = 0.f;
    matvec32(wb, z, q);
    {
        float acc[32];
        #pragma unroll
        for (int i = 0; i < 32; i++) acc[i] = 0.f;
        matvec32(wb + 1024, z, acc);
        float4* kw = reinterpret_cast<float4*>(Ksm + t * KV_STRIDE);
        #pragma unroll
        for (int j4 = 0; j4 < 8; j4++)
            kw[j4] = make_float4(acc[4*j4], acc[4*j4+1], acc[4*j4+2], acc[4*j4+3]);
    }
    {
        float acc[32];
        #pragma unroll
        for (int i = 0; i < 32; i++) acc[i] = 0.f;
        matvec32(wb + 2048, z, acc);
        float4* vw = reinterpret_cast<float4*>(Vsm + t * KV_STRIDE);
        #pragma unroll
        for (int j4 = 0; j4 < 8; j4++)
            vw[j4] = make_float4(acc[4*j4], acc[4*j4+1], acc[4*j4+2], acc[4*j4+3]);
    }
    __syncthreads();

    // ---- attention over this expert's keys + aggregated const key ----
    const float att_scale = 0.3535533905932738f; // 1/sqrt(8)
    const int koff = sI[e];
    const int kend = koff + sI[4 + e];

    float o[32];
    #pragma unroll
    for (int i = 0; i < 32; i++) o[i] = 0.f;
    float lsum[4] = {0.f, 0.f, 0.f, 0.f};

    for (int key = koff; key < kend; key++) {
        const float4* kr = reinterpret_cast<const float4*>(Ksm + key * KV_STRIDE);
        const float4* vr = reinterpret_cast<const float4*>(Vsm + key * KV_STRIDE);
        #pragma unroll
        for (int hh = 0; hh < 4; hh++) {
            float4 ka = kr[2 * hh], kb = kr[2 * hh + 1];
            float lg = q[8*hh + 0] * ka.x;
            lg = fmaf(q[8*hh + 1], ka.y, lg);
            lg = fmaf(q[8*hh + 2], ka.z, lg);
            lg = fmaf(q[8*hh + 3], ka.w, lg);
            lg = fmaf(q[8*hh + 4], kb.x, lg);
            lg = fmaf(q[8*hh + 5], kb.y, lg);
            lg = fmaf(q[8*hh + 6], kb.z, lg);
            lg = fmaf(q[8*hh + 7], kb.w, lg);
            float p = __expf(fminf(lg * att_scale, 80.f));
            lsum[hh] += p;
            float4 va = vr[2 * hh], vb = vr[2 * hh + 1];
            o[8*hh + 0] = fmaf(p, va.x, o[8*hh + 0]);
            o[8*hh + 1] = fmaf(p, va.y, o[8*hh + 1]);
            o[8*hh + 2] = fmaf(p, va.z, o[8*hh + 2]);
            o[8*hh + 3] = fmaf(p, va.w, o[8*hh + 3]);
            o[8*hh + 4] = fmaf(p, vb.x, o[8*hh + 4]);
            o[8*hh + 5] = fmaf(p, vb.y, o[8*hh + 5]);
            o[8*hh + 6] = fmaf(p, vb.z, o[8*hh + 6]);
            o[8*hh + 7] = fmaf(p, vb.w, o[8*hh + 7]);
        }
    }
    {
        const float w = (float)(SB - sI[4 + e]);
        const float4* kr = reinterpret_cast<const float4*>(sKc + e * 32);
        const float4* vr = reinterpret_cast<const float4*>(sVc + e * 32);
        #pragma unroll
        for (int hh = 0; hh < 4; hh++) {
            float4 ka = kr[2 * hh], kb = kr[2 * hh + 1];
            float lg = q[8*hh + 0] * ka.x;
            lg = fmaf(q[8*hh + 1], ka.y, lg);
            lg = fmaf(q[8*hh + 2], ka.z, lg);
            lg = fmaf(q[8*hh + 3], ka.w, lg);
            lg = fmaf(q[8*hh + 4], kb.x, lg);
            lg = fmaf(q[8*hh + 5], kb.y, lg);
            lg = fmaf(q[8*hh + 6], kb.z, lg);
            lg = fmaf(q[8*hh + 7], kb.w, lg);
            float p = w * __expf(fminf(lg * att_scale, 80.f));
            lsum[hh] += p;
            float4 va = vr[2 * hh], vb = vr[2 * hh + 1];
            o[8*hh + 0] = fmaf(p, va.x, o[8*hh + 0]);
            o[8*hh + 1] = fmaf(p, va.y, o[8*hh + 1]);
            o[8*hh + 2] = fmaf(p, va.z, o[8*hh + 2]);
            o[8*hh + 3] = fmaf(p, va.w, o[8*hh + 3]);
            o[8*hh + 4] = fmaf(p, vb.x, o[8*hh + 4]);
            o[8*hh + 5] = fmaf(p, vb.y, o[8*hh + 5]);
            o[8*hh + 6] = fmaf(p, vb.z, o[8*hh + 6]);
            o[8*hh + 7] = fmaf(p, vb.w, o[8*hh + 7]);
        }
    }
    #pragma unroll
    for (int hh = 0; hh < 4; hh++) {
        float inv = 1.0f / lsum[hh];
        #pragma unroll
        for (int d = 0; d < 8; d++) o[8*hh + d] *= inv;
    }

    // ---- h2 = h + o @ Wo ----
    float h2[32];
    #pragma unroll
    for (int d = 0; d < 32; d++) h2[d] = fmaf(xval, ssW[d], ssb[d]);
    matvec32(wb + 3072, o, h2);

    // ---- z2 = LN2(h2) ----
    float z2[32];
    {
        float mean = 0.f;
        #pragma unroll
        for (int d = 0; d < 32; d++) mean += h2[d];
        mean *= (1.f / 32.f);
        float var = 0.f;
        #pragma unroll
        for (int d = 0; d < 32; d++) { float dd = h2[d] - mean; var = fmaf(dd, dd, var); }
        var *= (1.f / 32.f);
        float r = rsqrtf(var + 1e-5f);
        #pragma unroll
        for (int d = 0; d < 32; d++)
            z2[d] = fmaf((h2[d] - mean) * r, l2g_[d], l2b_[d]);
    }

    // ---- FFN: h3 = h2 + relu(z2@W1 + b1)@W2 + b2, two 32-wide halves ----
    float h3[32];
    #pragma unroll
    for (int d = 0; d < 32; d++) h3[d] = h2[d] + b2_[d];

    const float* sW1 = wb + 4096;
    const float* sW2 = wb + 6144;
    #pragma unroll
    for (int half = 0; half < 2; half++) {
        float fh[32];
        #pragma unroll
        for (int j = 0; j < 32; j++) fh[j] = b1_[half * 32 + j];
        #pragma unroll
        for (int k2 = 0; k2 < 32; k2++) {
            float zz = z2[k2];
            const float4* wr = reinterpret_cast<const float4*>(sW1 + k2 * 64 + half * 32);
            #pragma unroll
            for (int j4 = 0; j4 < 8; j4++) {
                float4 w = wr[j4];
                fh[j4*4 + 0] = fmaf(zz, w.x, fh[j4*4 + 0]);
                fh[j4*4 + 1] = fmaf(zz, w.y, fh[j4*4 + 1]);
                fh[j4*4 + 2] = fmaf(zz, w.z, fh[j4*4 + 2]);
                fh[j4*4 + 3] = fmaf(zz, w.w, fh[j4*4 + 3]);
            }
        }
        #pragma unroll
        for (int j = 0; j < 32; j++) fh[j] = fmaxf(fh[j], 0.f);
        #pragma unroll
        for (int j = 0; j < 32; j++) {
            float fj = fh[j];
            const float4* wr = reinterpret_cast<const float4*>(sW2 + (half * 32 + j) * 32);
            #pragma unroll
            for (int d4 = 0; d4 < 8; d4++) {
                float4 w = wr[d4];
                h3[d4*4 + 0] = fmaf(fj, w.x, h3[d4*4 + 0]);
                h3[d4*4 + 1] = fmaf(fj, w.y, h3[d4*4 + 1]);
                h3[d4*4 + 2] = fmaf(fj, w.z, h3[d4*4 + 2]);
                h3[d4*4 + 3] = fmaf(fj, w.w, h3[d4*4 + 3]);
            }
        }
    }

    // ---- write: each (b,s) pair handled by exactly one thread per (n) ----
    {
        const int bs = b * SB + s;
        float4* op = reinterpret_cast<float4*>(out + ((bs * NB) + n) * DB);
        #pragma unroll
        for (int d4 = 0; d4 < 8; d4++)
            op[d4] = make_float4(h3[4*d4], h3[4*d4+1], h3[4*d4+2], h3[4*d4+3]);
    }
}

// ---------------------------------------------------------------------------
extern "C" void kernel_launch(void* const* d_in, const int* in_sizes, int n_in,
                              void* d_out, int out_size)
{
    const float* x      = (const float*)d_in[0];
    const float* orig   = (const float*)d_in[1];
    const float* startW = (const float*)d_in[2];
    const float* startb = (const float*)d_in[3];
    const float* Wq     = (const float*)d_in[4];
    const float* Wk     = (const float*)d_in[5];
    const float* Wv     = (const float*)d_in[6];
    const float* Wo     = (const float*)d_in[7];
    const float* l1g    = (const float*)d_in[8];
    const float* l1b    = (const float*)d_in[9];
    const float* l2g    = (const float*)d_in[10];
    const float* l2b    = (const float*)d_in[11];
    const float* W1     = (const float*)d_in[12];
    const float* b1     = (const float*)d_in[13];
    const float* W2     = (const float*)d_in[14];
    const float* b2     = (const float*)d_in[15];
    float* out = (float*)d_out;

    preprocess_kernel<<<dim3(NB, BB), 256>>>(x);
    assign_kernel<<<1, 256>>>(orig);

    const int smem_bytes = SMEM_FLOATS * (int)sizeof(float);
    cudaFuncSetAttribute(expert_kernel,
                         cudaFuncAttributeMaxDynamicSharedMemorySize, smem_bytes);
    expert_kernel<<<dim3(NB, BB), 256, smem_bytes>>>(
        startW, startb, Wq, Wk, Wv, Wo,
        l1g, l1b, l2g, l2b, W1, b1, W2, b2, out);
}

// round 14
// speedup vs baseline: 7.4277x; 1.0853x over previous
#include <cuda_runtime.h>
#include <math.h>

// Problem constants
#define EB 4
#define BB 16
#define SB 256
#define CB 17
#define NB 16
#define DB 32
#define DFFB 64
#define HB 4
#define DHB 8

typedef unsigned long long ull;

// ---- packed fp32x2 helpers (sm_103a) ----
__device__ __forceinline__ ull pack2(float a, float b) {
    ull r; asm("mov.b64 %0, {%1, %2};" : "=l"(r) : "f"(a), "f"(b)); return r;
}
__device__ __forceinline__ void unpack2(ull v, float& a, float& b) {
    asm("mov.b64 {%0, %1}, %2;" : "=f"(a), "=f"(b) : "l"(v));
}
__device__ __forceinline__ ull ffma2(ull a, ull b, ull c) {
    ull d; asm("fma.rn.f32x2 %0, %1, %2, %3;" : "=l"(d) : "l"(a), "l"(b), "l"(c)); return d;
}
__device__ __forceinline__ ull fmul2(ull a, ull b) {
    ull d; asm("mul.rn.f32x2 %0, %1, %2;" : "=l"(d) : "l"(a), "l"(b)); return d;
}

// Scratch (device globals; no allocations allowed)
__device__ float g_xns[BB * SB * NB];   // new_x channels 0..15
__device__ int   g_glist[BB * SB];      // per-b compacted s-indices, sorted by (expert, s)
__device__ int   g_off[BB * EB];        // per-b start offset of expert e
__device__ int   g_ecnt[BB * EB];       // per-b count of expert e

// ---------------------------------------------------------------------------
// Kernel 1: decomposition preprocessing. One block per (b, c), c<16.
// ---------------------------------------------------------------------------
__global__ void preprocess_kernel(const float* __restrict__ x)
{
    __shared__ float xr[SB];
    __shared__ float ctab[SB], stab[SB];
    __shared__ float Xre[129], Xim[129], amp[129];
    __shared__ int   s_kept[128];
    __shared__ int   s_keptN;

    const int c = blockIdx.x;
    const int b = blockIdx.y;
    const int t = threadIdx.x;

    xr[t] = x[(b * SB + t) * CB + c];
    {
        const float W2PI = 6.283185307179586f / 256.f;
        float sn, cs;
        sincosf(t * W2PI, &sn, &cs);
        ctab[t] = cs; stab[t] = sn;
    }
    __syncthreads();

    // ---- trend: mean of moving averages with kernels 4, 8, 12 ----
    float tr = 0.f;
    {
        #pragma unroll
        for (int ki = 0; ki < 3; ki++) {
            const int k = (ki == 0) ? 4 : (ki == 1 ? 8 : 12);
            const int pf = (k - 1) >> 1;
            float a = 0.f;
            for (int j = 0; j < k; j++) {
                int idx = t + j - pf;
                idx = idx < 0 ? 0 : (idx > SB - 1 ? SB - 1 : idx);
                a += xr[idx];
            }
            tr += a / (float)k;
        }
        tr *= (1.f / 3.f);
    }

    // ---- rDFT: thread (f, half) sums u in [half*128, half*128+128) ----
    {
        const int f    = t >> 1;
        const int half = t & 1;
        const int u0   = half * 128;
        float re = 0.f, im = 0.f;
        float ssum = 0.f, asum = 0.f;
        #pragma unroll 4
        for (int uu = 0; uu < 128; uu++) {
            const int u = u0 + uu;
            const float xv = xr[u];
            const int ph = (f * u) & 255;
            re = fmaf(xv,  ctab[ph], re);
            im = fmaf(xv, -stab[ph], im);
            ssum += xv;
            asum += (u & 1) ? -xv : xv;
        }
        re   += __shfl_xor_sync(0xffffffffu, re, 1);
        im   += __shfl_xor_sync(0xffffffffu, im, 1);
        ssum += __shfl_xor_sync(0xffffffffu, ssum, 1);
        asum += __shfl_xor_sync(0xffffffffu, asum, 1);
        if (half == 0) {
            if (f == 0) {
                Xre[0] = ssum; Xim[0] = 0.f; amp[0] = 0.f;
                Xre[128] = asum; Xim[128] = 0.f; amp[128] = fabsf(asum);
            } else {
                Xre[f] = re; Xim[f] = im;
                amp[f] = sqrtf(re * re + im * im);
            }
        }
    }
    __syncthreads();

    // ---- top-4 threshold among f=1..128 ----
    if (t == 0) {
        float b0 = -1e30f, b1v = -1e30f, b2v = -1e30f, b3v = -1e30f;
        for (int f = 1; f <= 128; f++) {
            float a = amp[f];
            if (a > b3v) {
                if (a > b0)       { b3v = b2v; b2v = b1v; b1v = b0; b0 = a; }
                else if (a > b1v) { b3v = b2v; b2v = b1v; b1v = a; }
                else if (a > b2v) { b3v = b2v; b2v = a; }
                else              { b3v = a; }
            }
        }
        int cnt = 0;
        for (int f = 1; f <= 128; f++)
            if (amp[f] >= b3v) s_kept[cnt++] = f;
        s_keptN = cnt;
    }
    __syncthreads();

    // ---- inverse transform of masked spectrum ----
    float season = 0.f;
    const int kn = s_keptN;
    for (int ii = 0; ii < kn; ii++) {
        int f = s_kept[ii];
        int ph = (f * t) & 255;
        if (f == 128) {
            season += Xre[128] * ctab[ph];
        } else {
            season += 2.f * (Xre[f] * ctab[ph] - Xim[f] * stab[ph]);
        }
    }
    season *= (1.f / 256.f);

    g_xns[(b * SB + t) * NB + c] = xr[t] + season + tr;
}

// ---------------------------------------------------------------------------
// Kernel 2: min/max -> bins -> assignment -> per-b expert-sorted lists.
// ---------------------------------------------------------------------------
__global__ void assign_kernel(const float* __restrict__ orig)
{
    __shared__ float smn[256], smx[256];
    __shared__ float bins[EB + 1];
    __shared__ int   sA[BB * SB];
    const int t = threadIdx.x;

    float mn = 1e30f, mx = -1e30f;
    for (int i = t; i < BB * SB; i += 256) {
        float v = orig[2 * i + 1];
        mn = fminf(mn, v);
        mx = fmaxf(mx, v);
    }
    smn[t] = mn; smx[t] = mx;
    __syncthreads();
    for (int off = 128; off > 0; off >>= 1) {
        if (t < off) {
            smn[t] = fminf(smn[t], smn[t + off]);
            smx[t] = fmaxf(smx[t], smx[t + off]);
        }
        __syncthreads();
    }
    if (t == 0) {
        float lo = smn[0], hi = smx[0];
        float st = (hi - lo) * 0.25f;
        for (int j = 0; j <= EB; j++) bins[j] = lo + j * st;
    }
    __syncthreads();
    for (int i = t; i < BB * SB; i += 256) {
        float v = orig[2 * i + 1];
        int cnt = 0;
        #pragma unroll
        for (int j = 0; j <= EB; j++) cnt += (bins[j] <= v) ? 1 : 0;
        int a = cnt - 1;
        a = a < 0 ? 0 : (a > EB - 1 ? EB - 1 : a);
        sA[i] = a;
    }
    __syncthreads();

    if (t < BB) {
        const int base = t * SB;
        int cnt[EB] = {0, 0, 0, 0};
        for (int s = 0; s < SB; s++) cnt[sA[base + s]]++;
        int off[EB];
        off[0] = 0;
        #pragma unroll
        for (int e = 1; e < EB; e++) off[e] = off[e - 1] + cnt[e - 1];
        #pragma unroll
        for (int e = 0; e < EB; e++) {
            g_off[t * EB + e]  = off[e];
            g_ecnt[t * EB + e] = cnt[e];
        }
        int pos[EB];
        #pragma unroll
        for (int e = 0; e < EB; e++) pos[e] = off[e];
        for (int s = 0; s < SB; s++) {
            int a = sA[base + s];
            g_glist[base + pos[a]] = s;
            pos[a]++;
        }
    }
}

// ---------------------------------------------------------------------------
// Packed 32x32 matvec: Wsm row-major [k][j], vin scalar[32], acc = 16 pairs.
// Per-element accumulation order identical to the scalar version.
// ---------------------------------------------------------------------------
__device__ __forceinline__ void matvec32p(const float* __restrict__ Wsm,
                                          const float (&vin)[32],
                                          ull (&acc)[16])
{
    #pragma unroll
    for (int k2 = 0; k2 < 32; k2++) {
        const ull zz = pack2(vin[k2], vin[k2]);
        const ulonglong2* wr = reinterpret_cast<const ulonglong2*>(Wsm + k2 * 32);
        #pragma unroll
        for (int j = 0; j < 8; j++) {
            const ulonglong2 w = wr[j];
            acc[2*j]     = ffma2(zz, w.x, acc[2*j]);
            acc[2*j + 1] = ffma2(zz, w.y, acc[2*j + 1]);
        }
    }
}

// ---------------------------------------------------------------------------
// Kernel 3: merged 4-expert forward, packed f32x2 math. Block (n,b), 256 thr.
// ---------------------------------------------------------------------------
#define WSTR   8192
#define KV_STRIDE 36
#define OFF_LN1G 32768
#define OFF_LN1B 32896
#define OFF_LN2G 33024
#define OFF_LN2B 33152
#define OFF_B1   33280
#define OFF_B2   33536
#define OFF_SSW  33664
#define OFF_SSB  33696
#define OFF_KC   33728
#define OFF_VC   33856
#define OFF_INTS 33984
#define OFF_K    34048
#define OFF_V    (34048 + SB * KV_STRIDE)
#define SMEM_FLOATS (OFF_V + SB * KV_STRIDE)

__global__ void __launch_bounds__(256, 1) expert_kernel(
    const float* __restrict__ startW, const float* __restrict__ startb,
    const float* __restrict__ Wq, const float* __restrict__ Wk,
    const float* __restrict__ Wv, const float* __restrict__ Wo,
    const float* __restrict__ ln1g, const float* __restrict__ ln1b,
    const float* __restrict__ ln2g, const float* __restrict__ ln2b,
    const float* __restrict__ W1, const float* __restrict__ b1,
    const float* __restrict__ W2, const float* __restrict__ b2,
    float* __restrict__ out)
{
    extern __shared__ float sm[];
    float* sKc = sm + OFF_KC;
    float* sVc = sm + OFF_VC;
    float* Ksm = sm + OFF_K;
    float* Vsm = sm + OFF_V;
    int*   sI  = reinterpret_cast<int*>(sm + OFF_INTS);

    const int t = threadIdx.x;
    const int n = blockIdx.x, b = blockIdx.y;

    // ---- stage all 4 experts' weights ----
    {
        const float4* gq = reinterpret_cast<const float4*>(Wq);
        const float4* gk = reinterpret_cast<const float4*>(Wk);
        const float4* gv = reinterpret_cast<const float4*>(Wv);
        const float4* go = reinterpret_cast<const float4*>(Wo);
        #pragma unroll
        for (int i = t; i < 1024; i += 256) {
            const int e = i >> 8, idx = i & 255;
            float4* dst = reinterpret_cast<float4*>(sm + e * WSTR);
            dst[idx]        = gq[i];
            dst[256 + idx]  = gk[i];
            dst[512 + idx]  = gv[i];
            dst[768 + idx]  = go[i];
        }
        const float4* g1 = reinterpret_cast<const float4*>(W1);
        const float4* g2 = reinterpret_cast<const float4*>(W2);
        #pragma unroll
        for (int i = t; i < 2048; i += 256) {
            const int e = i >> 9, idx = i & 511;
            float4* dst = reinterpret_cast<float4*>(sm + e * WSTR + 4096);
            dst[idx]        = g1[i];
            dst[512 + idx]  = g2[i];
        }
        if (t < 128) {
            sm[OFF_LN1G + t] = ln1g[t];
            sm[OFF_LN1B + t] = ln1b[t];
            sm[OFF_LN2G + t] = ln2g[t];
            sm[OFF_LN2B + t] = ln2b[t];
            sm[OFF_B2 + t]   = b2[t];
        }
        sm[OFF_B1 + t] = b1[t];
        if (t < 32) {
            sm[OFF_SSW + t] = startW[t];
            sm[OFF_SSB + t] = startb[t];
        }
        if (t < 4) {
            sI[t]     = g_off[b * EB + t];
            sI[4 + t] = g_ecnt[b * EB + t];
        }
    }
    __syncthreads();

    const float* ssW = sm + OFF_SSW;
    const float* ssb = sm + OFF_SSB;

    // ---- per-expert constant key/value (h_const = start_b) ----
    if (t < 128) {
        const int ce = t >> 5;
        const int d  = t & 31;
        float m = 0.f;
        #pragma unroll
        for (int dd = 0; dd < 32; dd++) m += ssb[dd];
        m *= (1.f / 32.f);
        float var = 0.f;
        #pragma unroll
        for (int dd = 0; dd < 32; dd++) { float df = ssb[dd] - m; var = fmaf(df, df, var); }
        var *= (1.f / 32.f);
        const float r = rsqrtf(var + 1e-5f);
        const float* l1g_ = sm + OFF_LN1G + ce * 32;
        const float* l1b_ = sm + OFF_LN1B + ce * 32;
        const float* wk_  = sm + ce * WSTR + 1024;
        const float* wv_  = sm + ce * WSTR + 2048;
        float kc = 0.f, vc = 0.f;
        #pragma unroll
        for (int k2 = 0; k2 < 32; k2++) {
            float zc = fmaf((ssb[k2] - m) * r, l1g_[k2], l1b_[k2]);
            kc = fmaf(zc, wk_[k2 * 32 + d], kc);
            vc = fmaf(zc, wv_[k2 * 32 + d], vc);
        }
        sKc[ce * 32 + d] = kc;
        sVc[ce * 32 + d] = vc;
    }

    // ---- this thread's query ----
    const int e = (t >= sI[1]) + (t >= sI[2]) + (t >= sI[3]);
    const int s = g_glist[b * SB + t];
    const float xval = g_xns[(b * SB + s) * NB + n];

    const float* wb   = sm + e * WSTR;
    const float* l1g_ = sm + OFF_LN1G + e * 32;
    const float* l1b_ = sm + OFF_LN1B + e * 32;
    const float* l2g_ = sm + OFF_LN2G + e * 32;
    const float* l2b_ = sm + OFF_LN2B + e * 32;
    const float* b1_  = sm + OFF_B1 + e * 64;
    const float* b2_  = sm + OFF_B2 + e * 32;

    // ---- z = LN1(xval*startW + startb) ----
    float z[32];
    {
        float mean = 0.f;
        #pragma unroll
        for (int d = 0; d < 32; d++) { z[d] = fmaf(xval, ssW[d], ssb[d]); mean += z[d]; }
        mean *= (1.f / 32.f);
        float var = 0.f;
        #pragma unroll
        for (int d = 0; d < 32; d++) { float dd = z[d] - mean; var = fmaf(dd, dd, var); }
        var *= (1.f / 32.f);
        float r = rsqrtf(var + 1e-5f);
        #pragma unroll
        for (int d = 0; d < 32; d++)
            z[d] = fmaf((z[d] - mean) * r, l1g_[d], l1b_[d]);
    }

    // ---- q (packed, scale folded in), k/v -> smem row t ----
    const float att_scale = 0.3535533905932738f; // 1/sqrt(8)
    ull q2[16];
    {
        #pragma unroll
        for (int i = 0; i < 16; i++) q2[i] = 0ull;
        matvec32p(wb, z, q2);
        const ull sc2 = pack2(att_scale, att_scale);
        #pragma unroll
        for (int i = 0; i < 16; i++) q2[i] = fmul2(q2[i], sc2);
    }
    {
        ull acc[16];
        #pragma unroll
        for (int i = 0; i < 16; i++) acc[i] = 0ull;
        matvec32p(wb + 1024, z, acc);
        ulonglong2* kw = reinterpret_cast<ulonglong2*>(Ksm + t * KV_STRIDE);
        #pragma unroll
        for (int j = 0; j < 8; j++) {
            ulonglong2 v; v.x = acc[2*j]; v.y = acc[2*j+1];
            kw[j] = v;
        }
    }
    {
        ull acc[16];
        #pragma unroll
        for (int i = 0; i < 16; i++) acc[i] = 0ull;
        matvec32p(wb + 2048, z, acc);
        ulonglong2* vw = reinterpret_cast<ulonglong2*>(Vsm + t * KV_STRIDE);
        #pragma unroll
        for (int j = 0; j < 8; j++) {
            ulonglong2 v; v.x = acc[2*j]; v.y = acc[2*j+1];
            vw[j] = v;
        }
    }
    __syncthreads();

    // ---- attention: this expert's keys + aggregated const key ----
    const int koff = sI[e];
    const int kend = koff + sI[4 + e];

    ull o2[16];
    #pragma unroll
    for (int i = 0; i < 16; i++) o2[i] = 0ull;
    float lsum[4] = {0.f, 0.f, 0.f, 0.f};

    #pragma unroll 2
    for (int key = koff; key < kend; key++) {
        const ulonglong2* kr = reinterpret_cast<const ulonglong2*>(Ksm + key * KV_STRIDE);
        const ulonglong2* vr = reinterpret_cast<const ulonglong2*>(Vsm + key * KV_STRIDE);
        #pragma unroll
        for (int hh = 0; hh < 4; hh++) {
            const ulonglong2 k01 = kr[2*hh], k23 = kr[2*hh + 1];
            ull lg2 = fmul2(q2[4*hh], k01.x);
            lg2 = ffma2(q2[4*hh + 1], k01.y, lg2);
            lg2 = ffma2(q2[4*hh + 2], k23.x, lg2);
            lg2 = ffma2(q2[4*hh + 3], k23.y, lg2);
            float lo, hi;
            unpack2(lg2, lo, hi);
            const float p = __expf(fminf(lo + hi, 80.f));
            lsum[hh] += p;
            const ull pp = pack2(p, p);
            const ulonglong2 v01 = vr[2*hh], v23 = vr[2*hh + 1];
            o2[4*hh]     = ffma2(pp, v01.x, o2[4*hh]);
            o2[4*hh + 1] = ffma2(pp, v01.y, o2[4*hh + 1]);
            o2[4*hh + 2] = ffma2(pp, v23.x, o2[4*hh + 2]);
            o2[4*hh + 3] = ffma2(pp, v23.y, o2[4*hh + 3]);
        }
    }
    {
        const float w = (float)(SB - sI[4 + e]);
        const ulonglong2* kr = reinterpret_cast<const ulonglong2*>(sKc + e * 32);
        const ulonglong2* vr = reinterpret_cast<const ulonglong2*>(sVc + e * 32);
        #pragma unroll
        for (int hh = 0; hh < 4; hh++) {
            const ulonglong2 k01 = kr[2*hh], k23 = kr[2*hh + 1];
            ull lg2 = fmul2(q2[4*hh], k01.x);
            lg2 = ffma2(q2[4*hh + 1], k01.y, lg2);
            lg2 = ffma2(q2[4*hh + 2], k23.x, lg2);
            lg2 = ffma2(q2[4*hh + 3], k23.y, lg2);
            float lo, hi;
            unpack2(lg2, lo, hi);
            const float p = w * __expf(fminf(lo + hi, 80.f));
            lsum[hh] += p;
            const ull pp = pack2(p, p);
            const ulonglong2 v01 = vr[2*hh], v23 = vr[2*hh + 1];
            o2[4*hh]     = ffma2(pp, v01.x, o2[4*hh]);
            o2[4*hh + 1] = ffma2(pp, v01.y, o2[4*hh + 1]);
            o2[4*hh + 2] = ffma2(pp, v23.x, o2[4*hh + 2]);
            o2[4*hh + 3] = ffma2(pp, v23.y, o2[4*hh + 3]);
        }
    }

    // normalize o
    float o[32];
    #pragma unroll
    for (int hh = 0; hh < 4; hh++) {
        const float inv = 1.0f / lsum[hh];
        #pragma unroll
        for (int j = 0; j < 4; j++) {
            float a, c;
            unpack2(o2[4*hh + j], a, c);
            o[8*hh + 2*j]     = a * inv;
            o[8*hh + 2*j + 1] = c * inv;
        }
    }

    // ---- h2 = h + o @ Wo  (packed acc seeded with residual) ----
    float h2[32];
    {
        ull acc[16];
        #pragma unroll
        for (int j = 0; j < 16; j++) {
            const float r0 = fmaf(xval, ssW[2*j],     ssb[2*j]);
            const float r1 = fmaf(xval, ssW[2*j + 1], ssb[2*j + 1]);
            acc[j] = pack2(r0, r1);
        }
        matvec32p(wb + 3072, o, acc);
        #pragma unroll
        for (int j = 0; j < 16; j++) unpack2(acc[j], h2[2*j], h2[2*j + 1]);
    }

    // ---- z2 = LN2(h2) ----
    float z2[32];
    {
        float mean = 0.f;
        #pragma unroll
        for (int d = 0; d < 32; d++) mean += h2[d];
        mean *= (1.f / 32.f);
        float var = 0.f;
        #pragma unroll
        for (int d = 0; d < 32; d++) { float dd = h2[d] - mean; var = fmaf(dd, dd, var); }
        var *= (1.f / 32.f);
        float r = rsqrtf(var + 1e-5f);
        #pragma unroll
        for (int d = 0; d < 32; d++)
            z2[d] = fmaf((h2[d] - mean) * r, l2g_[d], l2b_[d]);
    }

    // ---- FFN: h3 = h2 + relu(z2@W1 + b1)@W2 + b2, two 32-wide halves ----
    ull h32[16];
    #pragma unroll
    for (int j = 0; j < 16; j++)
        h32[j] = pack2(h2[2*j] + b2_[2*j], h2[2*j + 1] + b2_[2*j + 1]);

    const float* sW1 = wb + 4096;
    const float* sW2 = wb + 6144;
    #pragma unroll
    for (int half = 0; half < 2; half++) {
        // fh2 = z2 @ W1[:, half*32 .. half*32+32) + b1  (16 packed pairs = 32 floats)
        ull fh2[16];
        #pragma unroll
        for (int j = 0; j < 16; j++)
            fh2[j] = pack2(b1_[half*32 + 2*j], b1_[half*32 + 2*j + 1]);
        #pragma unroll
        for (int k2 = 0; k2 < 32; k2++) {
            const ull zz = pack2(z2[k2], z2[k2]);
            const ulonglong2* wr =
                reinterpret_cast<const ulonglong2*>(sW1 + k2 * 64 + half * 32);
            #pragma unroll
            for (int j = 0; j < 16; j++) {            // FIXED: 16 pairs, not 8
                const ulonglong2 w = wr[j >> 1];      // 4 floats per ulonglong2
                fh2[j] = ffma2(zz, (j & 1) ? w.y : w.x, fh2[j]);
            }
        }
        // relu (scalar), then second GEMM packed into h32
        float fh[32];
        #pragma unroll
        for (int j = 0; j < 16; j++) {
            float a, c;
            unpack2(fh2[j], a, c);
            fh[2*j]     = fmaxf(a, 0.f);
            fh[2*j + 1] = fmaxf(c, 0.f);
        }
        #pragma unroll
        for (int j = 0; j < 32; j++) {
            const ull fj = pack2(fh[j], fh[j]);
            const ulonglong2* wr =
                reinterpret_cast<const ulonglong2*>(sW2 + (half * 32 + j) * 32);
            #pragma unroll
            for (int d = 0; d < 16; d++) {            // FIXED: 16 pairs, not 8
                const ulonglong2 w = wr[d >> 1];
                h32[d] = ffma2(fj, (d & 1) ? w.y : w.x, h32[d]);
            }
        }
    }

    // ---- write: each (b,s) handled by exactly one thread per n ----
    {
        const int bs = b * SB + s;
        ulonglong2* op = reinterpret_cast<ulonglong2*>(out + ((bs * NB) + n) * DB);
        #pragma unroll
        for (int j = 0; j < 8; j++) {
            ulonglong2 v; v.x = h32[2*j]; v.y = h32[2*j + 1];
            op[j] = v;
        }
    }
}

// ---------------------------------------------------------------------------
extern "C" void kernel_launch(void* const* d_in, const int* in_sizes, int n_in,
                              void* d_out, int out_size)
{
    const float* x      = (const float*)d_in[0];
    const float* orig   = (const float*)d_in[1];
    const float* startW = (const float*)d_in[2];
    const float* startb = (const float*)d_in[3];
    const float* Wq     = (const float*)d_in[4];
    const float* Wk     = (const float*)d_in[5];
    const float* Wv     = (const float*)d_in[6];
    const float* Wo     = (const float*)d_in[7];
    const float* l1g    = (const float*)d_in[8];
    const float* l1b    = (const float*)d_in[9];
    const float* l2g    = (const float*)d_in[10];
    const float* l2b    = (const float*)d_in[11];
    const float* W1     = (const float*)d_in[12];
    const float* b1     = (const float*)d_in[13];
    const float* W2     = (const float*)d_in[14];
    const float* b2     = (const float*)d_in[15];
    float* out = (float*)d_out;

    preprocess_kernel<<<dim3(NB, BB), 256>>>(x);
    assign_kernel<<<1, 256>>>(orig);

    const int smem_bytes = SMEM_FLOATS * (int)sizeof(float);
    cudaFuncSetAttribute(expert_kernel,
                         cudaFuncAttributeMaxDynamicSharedMemorySize, smem_bytes);
    expert_kernel<<<dim3(NB, BB), 256, smem_bytes>>>(
        startW, startb, Wq, Wk, Wv, Wo,
        l1g, l1b, l2g, l2b, W1, b1, W2, b2, out);
}